// round 2
// baseline (speedup 1.0000x reference)
#include <cuda_runtime.h>
#include <math.h>
#include <stdint.h>

// ---------------- static scratch (no allocations allowed) ----------------
#define NMAX   131072
#define TMAX   1700000

__device__ float g_msgs[(size_t)TMAX * 64];   // message buffer [T, 64]
__device__ int   g_colidx[TMAX];              // CSR: message-row per slot
__device__ int   g_counts[NMAX];
__device__ int   g_rowptr[NMAX + 1];
__device__ int   g_cursor[NMAX];
__device__ float g_hA[(size_t)NMAX * 64];
__device__ float g_hB[(size_t)NMAX * 64];
__device__ float g_maxmsg[(size_t)NMAX * 64];
__device__ int   g_bounds[257];
__device__ float g_agg[256 * 64];

// ---------------- math helpers ----------------
__device__ __forceinline__ float mishf(float x) {
    // mish(x) = x * tanh(softplus(x)) = x * t(t+2)/(t(t+2)+2), t = exp(x)
    if (x > 20.f) return x;
    float e = expf(x);
    float n = e * (e + 2.f);
    return x * (n / (n + 2.f));
}

__device__ __forceinline__ void smax_upd(float& m, float& s, float v) {
    if (v > m) { s = s * expf(12.f * (m - v)) + 1.f; m = v; }
    else       { s += expf(12.f * (v - m)); }
}

// ---------------- CSR build ----------------
__global__ void zero_counts_kernel(int n) {
    int i = blockIdx.x * blockDim.x + threadIdx.x;
    if (i < n) g_counts[i] = 0;
}

__global__ void count_kernel(const int* __restrict__ atoms, int n) {
    for (int i = blockIdx.x * blockDim.x + threadIdx.x; i < n; i += gridDim.x * blockDim.x)
        atomicAdd(&g_counts[atoms[i]], 1);
}

__global__ void scan_kernel(int n) {
    __shared__ int wsum[32];
    __shared__ int sbase_sh;
    int tid = threadIdx.x, lane = tid & 31, wid = tid >> 5;
    if (tid == 0) sbase_sh = 0;
    __syncthreads();
    for (int base = 0; base < n; base += 1024) {
        int i = base + tid;
        int v = (i < n) ? g_counts[i] : 0;
        int x = v;
        #pragma unroll
        for (int o = 1; o < 32; o <<= 1) {
            int y = __shfl_up_sync(0xFFFFFFFFu, x, o);
            if (lane >= o) x += y;
        }
        if (lane == 31) wsum[wid] = x;
        __syncthreads();
        if (wid == 0) {
            int s = wsum[lane];
            #pragma unroll
            for (int o = 1; o < 32; o <<= 1) {
                int y = __shfl_up_sync(0xFFFFFFFFu, s, o);
                if (lane >= o) s += y;
            }
            wsum[lane] = s;
        }
        __syncthreads();
        int winc = (wid > 0) ? wsum[wid - 1] : 0;
        int incl = x + winc;
        int excl = sbase_sh + incl - v;
        if (i < n) { g_rowptr[i] = excl; g_cursor[i] = excl; }
        __syncthreads();
        if (tid == 1023) sbase_sh += incl;
        __syncthreads();
    }
    if (threadIdx.x == 0) g_rowptr[n] = sbase_sh;
}

__global__ void fill_kernel(const int* __restrict__ atoms, int n, int rowOff) {
    for (int i = blockIdx.x * blockDim.x + threadIdx.x; i < n; i += gridDim.x * blockDim.x) {
        int node = atoms[i];
        int pos = atomicAdd(&g_cursor[node], 1);
        g_colidx[pos] = rowOff + i;
    }
}

// ---------------- relation MLP: gather + GEMM + mish + GEMM + residual ----------------
// x[m, S] gathered rows of h by atoms; y = x + mish(x@Wi+bi)@Wo+bo; write to g_msgs
template <int S, int A>
__global__ void __launch_bounds__(256)
rel_kernel2(const float* __restrict__ hext, int hsel,
            const int* __restrict__ atoms, int m,
            const float* __restrict__ Wi, const float* __restrict__ bi,
            const float* __restrict__ Wo, const float* __restrict__ bo,
            long long outOff)
{
    constexpr int BM = 64;
    constexpr int TN = S / 16;
    constexpr int S4 = S / 4;
    constexpr int XST = S + 4;                 // padded row stride (floats)
    constexpr int GLOADS = (BM * S4) / 256;    // gather float4 loads per thread
    constexpr int WLOADS = (4 * S) / 256;      // weight-tile float4 loads per thread

    extern __shared__ float sm[];
    float* xs = sm;                            // BM * XST
    float* ts = xs + BM * XST;                 // BM * XST
    float* ws = ts + BM * XST;                 // 16 * S
    int*   sidx = (int*)(ws + 16 * S);         // BM * A

    const float* h = (hsel == 0) ? hext : ((hsel == 1) ? g_hA : g_hB);
    float* out = g_msgs + outOff;

    const int tid = threadIdx.x;
    const int tx = tid & 15, ty = tid >> 4;
    const int row0 = blockIdx.x * BM;

    if (tid < BM * A) {
        int t = row0 * A + tid;
        sidx[tid] = (t < m * A) ? atoms[t] : 0;
    }
    __syncthreads();

    // gather x rows (float4); padded stride S4+1 float4s = XST floats
    const float4* h4 = (const float4*)h;
    float4* xs4 = (float4*)xs;
    #pragma unroll
    for (int v = 0; v < GLOADS; v++) {
        int u = tid + v * 256;
        int r = u / S4;
        int rem = u - r * S4;
        int node = sidx[r * A + (rem >> 4)];
        xs4[r * (S4 + 1) + rem] = h4[(size_t)node * 16 + (rem & 15)];
    }
    __syncthreads();

    float acc[4][TN];
    #pragma unroll
    for (int i = 0; i < 4; i++)
        #pragma unroll
        for (int j = 0; j < TN; j++) acc[i][j] = 0.f;

    const float4* Wi4 = (const float4*)Wi;
    float4* ws4 = (float4*)ws;

    // GEMM1: acc = x @ Wi
    for (int kt = 0; kt < S / 16; kt++) {
        #pragma unroll
        for (int v = 0; v < WLOADS; v++) {
            int u = tid + v * 256;
            ws4[u] = Wi4[kt * (4 * S) + u];    // 16 contiguous rows of Wi
        }
        __syncthreads();
        #pragma unroll
        for (int kk = 0; kk < 16; kk++) {
            float av[4];
            #pragma unroll
            for (int i = 0; i < 4; i++) av[i] = xs[(ty * 4 + i) * XST + kt * 16 + kk];
            float bv[TN];
            #pragma unroll
            for (int j = 0; j < TN; j++) bv[j] = ws[kk * S + tx + 16 * j];
            #pragma unroll
            for (int i = 0; i < 4; i++)
                #pragma unroll
                for (int j = 0; j < TN; j++) acc[i][j] = fmaf(av[i], bv[j], acc[i][j]);
        }
        __syncthreads();
    }

    // bias + mish -> ts
    #pragma unroll
    for (int j = 0; j < TN; j++) {
        float bj = bi[tx + 16 * j];
        #pragma unroll
        for (int i = 0; i < 4; i++)
            ts[(ty * 4 + i) * XST + tx + 16 * j] = mishf(acc[i][j] + bj);
    }
    __syncthreads();

    // GEMM2: acc = x + bo + mish(.) @ Wo
    #pragma unroll
    for (int j = 0; j < TN; j++) {
        float bj = bo[tx + 16 * j];
        #pragma unroll
        for (int i = 0; i < 4; i++)
            acc[i][j] = xs[(ty * 4 + i) * XST + tx + 16 * j] + bj;
    }
    const float4* Wo4 = (const float4*)Wo;
    for (int kt = 0; kt < S / 16; kt++) {
        #pragma unroll
        for (int v = 0; v < WLOADS; v++) {
            int u = tid + v * 256;
            ws4[u] = Wo4[kt * (4 * S) + u];
        }
        __syncthreads();
        #pragma unroll
        for (int kk = 0; kk < 16; kk++) {
            float av[4];
            #pragma unroll
            for (int i = 0; i < 4; i++) av[i] = ts[(ty * 4 + i) * XST + kt * 16 + kk];
            float bv[TN];
            #pragma unroll
            for (int j = 0; j < TN; j++) bv[j] = ws[kk * S + tx + 16 * j];
            #pragma unroll
            for (int i = 0; i < 4; i++)
                #pragma unroll
                for (int j = 0; j < TN; j++) acc[i][j] = fmaf(av[i], bv[j], acc[i][j]);
        }
        __syncthreads();
    }

    // write messages: tuple r occupies S contiguous floats at out + r*S
    #pragma unroll
    for (int i = 0; i < 4; i++) {
        int r = row0 + ty * 4 + i;
        if (r < m) {
            #pragma unroll
            for (int j = 0; j < TN; j++)
                out[(size_t)r * S + tx + 16 * j] = acc[i][j];
        }
    }
}

// ---------------- smooth-max aggregation (one warp per node) ----------------
__global__ void agg_kernel(int n) {
    int w = (blockIdx.x * blockDim.x + threadIdx.x) >> 5;
    if (w >= n) return;
    int lane = threadIdx.x & 31;
    int s = g_rowptr[w], e = g_rowptr[w + 1];

    float m1 = -INFINITY, m2 = -INFINITY, s1 = 0.f, s2 = 0.f;
    int i = s;
    for (; i + 2 <= e; i += 2) {
        int r0 = __ldg(&g_colidx[i]);
        int r1 = __ldg(&g_colidx[i + 1]);
        const float* p0 = g_msgs + (size_t)r0 * 64;
        const float* p1 = g_msgs + (size_t)r1 * 64;
        float a0 = p0[lane], a1 = p0[lane + 32];
        float b0 = p1[lane], b1 = p1[lane + 32];
        smax_upd(m1, s1, a0); smax_upd(m2, s2, a1);
        smax_upd(m1, s1, b0); smax_upd(m2, s2, b1);
    }
    if (i < e) {
        int r0 = __ldg(&g_colidx[i]);
        const float* p0 = g_msgs + (size_t)r0 * 64;
        smax_upd(m1, s1, p0[lane]); smax_upd(m2, s2, p0[lane + 32]);
    }
    if (s == e) { m1 = 0.f; m2 = 0.f; }   // empty segment: exps_max := 0

    const float inv = 1.f / 12.f;
    g_maxmsg[(size_t)w * 64 + lane]      = logf(1e-16f + s1) * inv + m1;
    g_maxmsg[(size_t)w * 64 + lane + 32] = logf(1e-16f + s2) * inv + m2;
}

// ---------------- update MLP: h += mish([maxmsg|h]@uWi+ubi)@uWo+ubo ----------------
__global__ void __launch_bounds__(256)
update_kernel(const float* __restrict__ hext, int hinsel, int houtsel, int n,
              const float* __restrict__ Wi, const float* __restrict__ bi,
              const float* __restrict__ Wo, const float* __restrict__ bo)
{
    constexpr int XST = 132;
    extern __shared__ float sm[];
    float* xs = sm;                 // 64*132
    float* ts = xs + 64 * XST;      // 64*132
    float* ws = ts + 64 * XST;      // 16*128

    const float* hin = (hinsel == 0) ? hext : ((hinsel == 1) ? g_hA : g_hB);
    float* hout = (houtsel == 1) ? g_hA : g_hB;

    const int tid = threadIdx.x;
    const int tx = tid & 15, ty = tid >> 4;
    const int row0 = blockIdx.x * 64;

    const float4* h4 = (const float4*)hin;
    const float4* mm4 = (const float4*)g_maxmsg;
    #pragma unroll
    for (int v = 0; v < 8; v++) {
        int u = tid + v * 256;
        int r = u >> 5, c4 = u & 31;
        float4 val = (c4 < 16) ? mm4[(size_t)(row0 + r) * 16 + c4]
                               : h4[(size_t)(row0 + r) * 16 + (c4 - 16)];
        ((float4*)xs)[r * 33 + c4] = val;
    }
    __syncthreads();

    float acc[4][8];
    #pragma unroll
    for (int i = 0; i < 4; i++)
        #pragma unroll
        for (int j = 0; j < 8; j++) acc[i][j] = 0.f;

    const float4* Wi4 = (const float4*)Wi;
    for (int kt = 0; kt < 8; kt++) {
        #pragma unroll
        for (int v = 0; v < 2; v++) {
            int u = tid + v * 256;
            ((float4*)ws)[u] = Wi4[kt * 512 + u];
        }
        __syncthreads();
        #pragma unroll
        for (int kk = 0; kk < 16; kk++) {
            float av[4];
            #pragma unroll
            for (int i = 0; i < 4; i++) av[i] = xs[(ty * 4 + i) * XST + kt * 16 + kk];
            float bv[8];
            #pragma unroll
            for (int j = 0; j < 8; j++) bv[j] = ws[kk * 128 + tx + 16 * j];
            #pragma unroll
            for (int i = 0; i < 4; i++)
                #pragma unroll
                for (int j = 0; j < 8; j++) acc[i][j] = fmaf(av[i], bv[j], acc[i][j]);
        }
        __syncthreads();
    }

    #pragma unroll
    for (int j = 0; j < 8; j++) {
        float bj = bi[tx + 16 * j];
        #pragma unroll
        for (int i = 0; i < 4; i++)
            ts[(ty * 4 + i) * XST + tx + 16 * j] = mishf(acc[i][j] + bj);
    }
    __syncthreads();

    float acc2[4][4];
    #pragma unroll
    for (int j = 0; j < 4; j++) {
        float bj = bo[tx + 16 * j];
        #pragma unroll
        for (int i = 0; i < 4; i++) {
            int r = row0 + ty * 4 + i;
            acc2[i][j] = hin[(size_t)r * 64 + tx + 16 * j] + bj;
        }
    }
    const float4* Wo4 = (const float4*)Wo;   // [128, 64]
    for (int kt = 0; kt < 8; kt++) {
        ((float4*)ws)[tid] = Wo4[kt * 256 + tid];
        __syncthreads();
        #pragma unroll
        for (int kk = 0; kk < 16; kk++) {
            float av[4];
            #pragma unroll
            for (int i = 0; i < 4; i++) av[i] = ts[(ty * 4 + i) * XST + kt * 16 + kk];
            float bv[4];
            #pragma unroll
            for (int j = 0; j < 4; j++) bv[j] = ws[kk * 64 + tx + 16 * j];
            #pragma unroll
            for (int i = 0; i < 4; i++)
                #pragma unroll
                for (int j = 0; j < 4; j++) acc2[i][j] = fmaf(av[i], bv[j], acc2[i][j]);
        }
        __syncthreads();
    }

    #pragma unroll
    for (int i = 0; i < 4; i++) {
        int r = row0 + ty * 4 + i;
        if (r < n) {
            #pragma unroll
            for (int j = 0; j < 4; j++)
                hout[(size_t)r * 64 + tx + 16 * j] = acc2[i][j];
        }
    }
}

// ---------------- readout ----------------
__global__ void bounds_kernel(const int* __restrict__ tok, int B) {
    if (threadIdx.x == 0) {
        int c = 0;
        g_bounds[0] = 0;
        for (int i = 0; i < B; i++) { c += tok[i]; g_bounds[i + 1] = c; }
    }
}

__global__ void segsum_kernel() {
    int b = blockIdx.x;
    int s = g_bounds[b], e = g_bounds[b + 1];
    int f = threadIdx.x & 63, g = threadIdx.x >> 6;
    float a = 0.f;
    for (int r = s + g; r < e; r += 4) a += g_hB[(size_t)r * 64 + f];
    __shared__ float red[256];
    red[threadIdx.x] = a;
    __syncthreads();
    if (g == 0) g_agg[b * 64 + f] = red[f] + red[64 + f] + red[128 + f] + red[192 + f];
}

__global__ void heads_kernel(const float* __restrict__ vWi, const float* __restrict__ vbi,
                             const float* __restrict__ vWo, const float* __restrict__ vbo,
                             const float* __restrict__ dWi, const float* __restrict__ dbi,
                             const float* __restrict__ dWo, const float* __restrict__ dbo,
                             float* __restrict__ out, int B)
{
    int b = blockIdx.x, o = threadIdx.x;   // 64 threads
    __shared__ float a[64];
    __shared__ float red[64];
    a[o] = g_agg[b * 64 + o];
    __syncthreads();

    float t = vbi[o];
    for (int i = 0; i < 64; i++) t = fmaf(a[i], vWi[i * 64 + o], t);
    red[o] = mishf(t) * vWo[o];
    __syncthreads();
    for (int s = 32; s > 0; s >>= 1) {
        if (o < s) red[o] += red[o + s];
        __syncthreads();
    }
    if (o == 0) out[b] = red[0] + vbo[0];
    __syncthreads();

    t = dbi[o];
    for (int i = 0; i < 64; i++) t = fmaf(a[i], dWi[i * 64 + o], t);
    red[o] = mishf(t) * dWo[o];
    __syncthreads();
    for (int s = 32; s > 0; s >>= 1) {
        if (o < s) red[o] += red[o + s];
        __syncthreads();
    }
    if (o == 0) out[B + b] = red[0] + dbo[0];
}

// ---------------- host launch ----------------
static inline int smem_rel(int S, int A) {
    return (2 * 64 * (S + 4) + 16 * S) * 4 + 64 * A * 4;
}

extern "C" void kernel_launch(void* const* d_in, const int* in_sizes, int n_in,
                              void* d_out, int out_size)
{
    if (n_in < 29) return;
    const float* h0  = (const float*)d_in[0];
    const int*   a1  = (const int*)d_in[1];  int n1 = in_sizes[1];
    const int*   a2  = (const int*)d_in[2];  int n2 = in_sizes[2];
    const int*   a3  = (const int*)d_in[3];  int n3 = in_sizes[3];
    const int*   tok = (const int*)d_in[4];  int B  = in_sizes[4];
    const float* Wi1 = (const float*)d_in[5],  *bi1 = (const float*)d_in[6];
    const float* Wo1 = (const float*)d_in[7],  *bo1 = (const float*)d_in[8];
    const float* Wi2 = (const float*)d_in[9],  *bi2 = (const float*)d_in[10];
    const float* Wo2 = (const float*)d_in[11], *bo2 = (const float*)d_in[12];
    const float* Wi3 = (const float*)d_in[13], *bi3 = (const float*)d_in[14];
    const float* Wo3 = (const float*)d_in[15], *bo3 = (const float*)d_in[16];
    const float* uWi = (const float*)d_in[17], *ubi = (const float*)d_in[18];
    const float* uWo = (const float*)d_in[19], *ubo = (const float*)d_in[20];
    const float* vWi = (const float*)d_in[21], *vbi = (const float*)d_in[22];
    const float* vWo = (const float*)d_in[23], *vbo = (const float*)d_in[24];
    const float* dWi = (const float*)d_in[25], *dbi = (const float*)d_in[26];
    const float* dWo = (const float*)d_in[27], *dbo = (const float*)d_in[28];
    float* out = (float*)d_out;

    int N = in_sizes[0] / 64;
    int m1 = n1, m2 = n2 / 2, m3 = n3 / 3;

    const int SM1 = smem_rel(64, 1);
    const int SM2 = smem_rel(128, 2);
    const int SM3 = smem_rel(192, 3);
    const int SMU = (2 * 64 * 132 + 16 * 128) * 4;

    cudaFuncSetAttribute(rel_kernel2<128, 2>, cudaFuncAttributeMaxDynamicSharedMemorySize, SM2);
    cudaFuncSetAttribute(rel_kernel2<192, 3>, cudaFuncAttributeMaxDynamicSharedMemorySize, SM3);
    cudaFuncSetAttribute(update_kernel,       cudaFuncAttributeMaxDynamicSharedMemorySize, SMU);

    // ---- CSR build (indices are fixed inputs; rebuilt deterministically each call) ----
    zero_counts_kernel<<<(N + 255) / 256, 256>>>(N);
    count_kernel<<<512, 256>>>(a1, n1);
    count_kernel<<<512, 256>>>(a2, n2);
    count_kernel<<<512, 256>>>(a3, n3);
    scan_kernel<<<1, 1024>>>(N);
    fill_kernel<<<512, 256>>>(a1, n1, 0);
    fill_kernel<<<512, 256>>>(a2, n2, n1);
    fill_kernel<<<512, 256>>>(a3, n3, n1 + n2);

    // ---- two GNN layers ----
    for (int layer = 0; layer < 2; layer++) {
        int hsel = (layer == 0) ? 0 : 1;
        rel_kernel2<64, 1><<<(m1 + 63) / 64, 256, SM1>>>(h0, hsel, a1, m1, Wi1, bi1, Wo1, bo1, 0LL);
        rel_kernel2<128, 2><<<(m2 + 63) / 64, 256, SM2>>>(h0, hsel, a2, m2, Wi2, bi2, Wo2, bo2, (long long)n1 * 64);
        rel_kernel2<192, 3><<<(m3 + 63) / 64, 256, SM3>>>(h0, hsel, a3, m3, Wi3, bi3, Wo3, bo3, (long long)(n1 + n2) * 64);
        agg_kernel<<<(N + 7) / 8, 256>>>(N);
        update_kernel<<<(N + 63) / 64, 256, SMU>>>(h0, hsel, (layer == 0) ? 1 : 2, N,
                                                   uWi, ubi, uWo, ubo);
    }

    // ---- readout ----
    bounds_kernel<<<1, 32>>>(tok, B);
    segsum_kernel<<<B, 256>>>();
    heads_kernel<<<B, 64>>>(vWi, vbi, vWo, vbo, dWi, dbi, dWo, dbo, out, B);
}

// round 3
// speedup vs baseline: 1.8960x; 1.8960x over previous
#include <cuda_runtime.h>
#include <math.h>
#include <stdint.h>

// ---------------- static scratch (no allocations allowed) ----------------
#define NMAX   131072
#define TMAX   1700000

__device__ float g_msgs[(size_t)TMAX * 64];   // message buffer [T, 64]
__device__ int   g_colidx[TMAX];              // CSR: message-row per slot
__device__ int   g_counts[NMAX];
__device__ int   g_rowptr[NMAX + 1];
__device__ int   g_cursor[NMAX];
__device__ float g_hA[(size_t)NMAX * 64];
__device__ float g_hB[(size_t)NMAX * 64];
__device__ float g_maxmsg[(size_t)NMAX * 64];
__device__ int   g_bounds[257];
__device__ float g_agg[256 * 64];

// ---------------- math helpers ----------------
__device__ __forceinline__ float mishf(float x) {
    if (x > 20.f) return x;
    float e = expf(x);
    float n = e * (e + 2.f);
    return x * (n / (n + 2.f));
}

__device__ __forceinline__ void smax_upd(float& m, float& s, float v) {
    if (v > m) { s = s * expf(12.f * (m - v)) + 1.f; m = v; }
    else       { s += expf(12.f * (v - m)); }
}

__device__ __forceinline__ unsigned f2tf(float x) {
    unsigned r;
    asm("cvt.rna.tf32.f32 %0, %1;" : "=r"(r) : "f"(x));
    return r;
}

__device__ __forceinline__ void mma8(float* c, unsigned a0, unsigned a1, unsigned a2, unsigned a3,
                                     unsigned b0, unsigned b1) {
    asm volatile(
        "mma.sync.aligned.m16n8k8.row.col.f32.tf32.tf32.f32 "
        "{%0,%1,%2,%3}, {%4,%5,%6,%7}, {%8,%9}, {%0,%1,%2,%3};\n"
        : "+f"(c[0]), "+f"(c[1]), "+f"(c[2]), "+f"(c[3])
        : "r"(a0), "r"(a1), "r"(a2), "r"(a3), "r"(b0), "r"(b1));
}

// ---------------- CSR build ----------------
__global__ void zero_counts_kernel(int n) {
    int i = blockIdx.x * blockDim.x + threadIdx.x;
    if (i < n) g_counts[i] = 0;
}

__global__ void count_kernel(const int* __restrict__ atoms, int n) {
    for (int i = blockIdx.x * blockDim.x + threadIdx.x; i < n; i += gridDim.x * blockDim.x)
        atomicAdd(&g_counts[atoms[i]], 1);
}

__global__ void scan_kernel(int n) {
    __shared__ int wsum[32];
    __shared__ int sbase_sh;
    int tid = threadIdx.x, lane = tid & 31, wid = tid >> 5;
    if (tid == 0) sbase_sh = 0;
    __syncthreads();
    for (int base = 0; base < n; base += 1024) {
        int i = base + tid;
        int v = (i < n) ? g_counts[i] : 0;
        int x = v;
        #pragma unroll
        for (int o = 1; o < 32; o <<= 1) {
            int y = __shfl_up_sync(0xFFFFFFFFu, x, o);
            if (lane >= o) x += y;
        }
        if (lane == 31) wsum[wid] = x;
        __syncthreads();
        if (wid == 0) {
            int s = wsum[lane];
            #pragma unroll
            for (int o = 1; o < 32; o <<= 1) {
                int y = __shfl_up_sync(0xFFFFFFFFu, s, o);
                if (lane >= o) s += y;
            }
            wsum[lane] = s;
        }
        __syncthreads();
        int winc = (wid > 0) ? wsum[wid - 1] : 0;
        int incl = x + winc;
        int excl = sbase_sh + incl - v;
        if (i < n) { g_rowptr[i] = excl; g_cursor[i] = excl; }
        __syncthreads();
        if (tid == 1023) sbase_sh += incl;
        __syncthreads();
    }
    if (threadIdx.x == 0) g_rowptr[n] = sbase_sh;
}

__global__ void fill_kernel(const int* __restrict__ atoms, int n, int rowOff) {
    for (int i = blockIdx.x * blockDim.x + threadIdx.x; i < n; i += gridDim.x * blockDim.x) {
        int node = atoms[i];
        int pos = atomicAdd(&g_cursor[node], 1);
        g_colidx[pos] = rowOff + i;
    }
}

// ---------------- relation MLP (TF32 tensor cores) ----------------
// x[m, S] gathered rows of h by atoms; y = x + mish(x@Wi+bi)@Wo+bo; write to g_msgs.
// Block: 256 thr (8 warps), tile 64 rows. Warp = (rg = w&1) 32 rows x (cg = w>>1) S/4 cols.
template <int S, int A>
__global__ void __launch_bounds__(256)
rel_kernel(const float* __restrict__ hext, int hsel,
           const int* __restrict__ atoms, int m,
           const float* __restrict__ Wi, const float* __restrict__ bi,
           const float* __restrict__ Wo, const float* __restrict__ bo,
           long long outOff)
{
    constexpr int BM  = 64;
    constexpr int NT  = S / 32;            // n-tiles per warp
    constexpr int KC  = S / 16;            // 16-row weight chunks
    constexpr int XST = S + 4;             // activation smem stride (=4 mod 32)
    constexpr int WST = S + 8;             // weight smem stride (=8 mod 32)
    constexpr int S4  = S / 4;

    extern __shared__ unsigned sm[];
    unsigned* xs = sm;                     // BM * XST (tf32 bits)
    unsigned* ts = xs + BM * XST;          // BM * XST
    unsigned* ws = ts + BM * XST;          // 16 * WST
    int* sidx = (int*)(ws + 16 * WST);     // BM * A

    const float* h = (hsel == 0) ? hext : ((hsel == 1) ? g_hA : g_hB);
    float* out = g_msgs + outOff;

    const int tid  = threadIdx.x;
    const int lane = tid & 31;
    const int warp = tid >> 5;
    const int rg   = warp & 1;
    const int cg   = warp >> 1;           // 0..3
    const int gid  = lane >> 2;           // 0..7
    const int ctg  = lane & 3;            // 0..3
    const int row0 = blockIdx.x * BM;

    if (tid < BM * A) {
        int t = row0 * A + tid;
        sidx[tid] = (t < m * A) ? atoms[t] : 0;
    }
    __syncthreads();

    // gather x rows -> tf32 smem
    const float4* h4 = (const float4*)h;
    #pragma unroll
    for (int v = 0; v < S / 16; v++) {
        int u = tid + v * 256;            // [0, BM*S4)
        int r = u / S4;
        int rem = u - r * S4;
        int node = sidx[r * A + (rem >> 4)];
        float4 val = h4[(size_t)node * 16 + (rem & 15)];
        uint4 tv = make_uint4(f2tf(val.x), f2tf(val.y), f2tf(val.z), f2tf(val.w));
        ((uint4*)xs)[r * (S4 + 1) + rem] = tv;
    }
    __syncthreads();

    float acc[2][NT][4];
    #pragma unroll
    for (int mt = 0; mt < 2; mt++)
        #pragma unroll
        for (int nt = 0; nt < NT; nt++)
            #pragma unroll
            for (int q = 0; q < 4; q++) acc[mt][nt][q] = 0.f;

    const int rb = rg * 32 + gid;
    const int cb = cg * (S / 4);

    // ---- GEMM1: acc = x @ Wi ----
    const float4* Wi4 = (const float4*)Wi;
    for (int kc = 0; kc < KC; kc++) {
        #pragma unroll
        for (int v = 0; v < S / 64; v++) {
            int u = tid + v * 256;        // [0, 4*S)
            int rr = u / S4, c4 = u - rr * S4;
            float4 w = Wi4[kc * 4 * S + u];
            ((uint4*)ws)[rr * (WST / 4) + c4] = make_uint4(f2tf(w.x), f2tf(w.y), f2tf(w.z), f2tf(w.w));
        }
        __syncthreads();
        #pragma unroll
        for (int ks = 0; ks < 2; ks++) {
            int acol = kc * 16 + ks * 8 + ctg;
            unsigned a[2][4];
            #pragma unroll
            for (int mt = 0; mt < 2; mt++) {
                const unsigned* ap = xs + (rb + mt * 16) * XST + acol;
                a[mt][0] = ap[0];
                a[mt][1] = ap[8 * XST];
                a[mt][2] = ap[4];
                a[mt][3] = ap[8 * XST + 4];
            }
            #pragma unroll
            for (int nt = 0; nt < NT; nt++) {
                int bcol = cb + nt * 8 + gid;
                unsigned b0 = ws[(ks * 8 + ctg) * WST + bcol];
                unsigned b1 = ws[(ks * 8 + ctg + 4) * WST + bcol];
                mma8(acc[0][nt], a[0][0], a[0][1], a[0][2], a[0][3], b0, b1);
                mma8(acc[1][nt], a[1][0], a[1][1], a[1][2], a[1][3], b0, b1);
            }
        }
        __syncthreads();
    }

    // ---- bias + mish -> ts ----
    #pragma unroll
    for (int mt = 0; mt < 2; mt++) {
        int rA = rg * 32 + mt * 16 + gid;
        #pragma unroll
        for (int nt = 0; nt < NT; nt++) {
            int c0 = cb + nt * 8 + 2 * ctg;
            float b0v = __ldg(&bi[c0]), b1v = __ldg(&bi[c0 + 1]);
            ts[rA * XST + c0]           = f2tf(mishf(acc[mt][nt][0] + b0v));
            ts[rA * XST + c0 + 1]       = f2tf(mishf(acc[mt][nt][1] + b1v));
            ts[(rA + 8) * XST + c0]     = f2tf(mishf(acc[mt][nt][2] + b0v));
            ts[(rA + 8) * XST + c0 + 1] = f2tf(mishf(acc[mt][nt][3] + b1v));
        }
    }

    // ---- GEMM2 init: acc = x + bo ----
    #pragma unroll
    for (int mt = 0; mt < 2; mt++) {
        int rA = rg * 32 + mt * 16 + gid;
        #pragma unroll
        for (int nt = 0; nt < NT; nt++) {
            int c0 = cb + nt * 8 + 2 * ctg;
            float b0v = __ldg(&bo[c0]), b1v = __ldg(&bo[c0 + 1]);
            acc[mt][nt][0] = __uint_as_float(xs[rA * XST + c0]) + b0v;
            acc[mt][nt][1] = __uint_as_float(xs[rA * XST + c0 + 1]) + b1v;
            acc[mt][nt][2] = __uint_as_float(xs[(rA + 8) * XST + c0]) + b0v;
            acc[mt][nt][3] = __uint_as_float(xs[(rA + 8) * XST + c0 + 1]) + b1v;
        }
    }

    // ---- GEMM2: acc += mish(.) @ Wo ----
    const float4* Wo4 = (const float4*)Wo;
    for (int kc = 0; kc < KC; kc++) {
        #pragma unroll
        for (int v = 0; v < S / 64; v++) {
            int u = tid + v * 256;
            int rr = u / S4, c4 = u - rr * S4;
            float4 w = Wo4[kc * 4 * S + u];
            ((uint4*)ws)[rr * (WST / 4) + c4] = make_uint4(f2tf(w.x), f2tf(w.y), f2tf(w.z), f2tf(w.w));
        }
        __syncthreads();
        #pragma unroll
        for (int ks = 0; ks < 2; ks++) {
            int acol = kc * 16 + ks * 8 + ctg;
            unsigned a[2][4];
            #pragma unroll
            for (int mt = 0; mt < 2; mt++) {
                const unsigned* ap = ts + (rb + mt * 16) * XST + acol;
                a[mt][0] = ap[0];
                a[mt][1] = ap[8 * XST];
                a[mt][2] = ap[4];
                a[mt][3] = ap[8 * XST + 4];
            }
            #pragma unroll
            for (int nt = 0; nt < NT; nt++) {
                int bcol = cb + nt * 8 + gid;
                unsigned b0 = ws[(ks * 8 + ctg) * WST + bcol];
                unsigned b1 = ws[(ks * 8 + ctg + 4) * WST + bcol];
                mma8(acc[0][nt], a[0][0], a[0][1], a[0][2], a[0][3], b0, b1);
                mma8(acc[1][nt], a[1][0], a[1][1], a[1][2], a[1][3], b0, b1);
            }
        }
        __syncthreads();
    }

    // ---- store messages ----
    #pragma unroll
    for (int mt = 0; mt < 2; mt++) {
        int rA = row0 + rg * 32 + mt * 16 + gid;
        #pragma unroll
        for (int nt = 0; nt < NT; nt++) {
            int c0 = cb + nt * 8 + 2 * ctg;
            if (rA < m) {
                out[(size_t)rA * S + c0]     = acc[mt][nt][0];
                out[(size_t)rA * S + c0 + 1] = acc[mt][nt][1];
            }
            if (rA + 8 < m) {
                out[(size_t)(rA + 8) * S + c0]     = acc[mt][nt][2];
                out[(size_t)(rA + 8) * S + c0 + 1] = acc[mt][nt][3];
            }
        }
    }
}

// ---------------- smooth-max aggregation (one warp per node) ----------------
__global__ void agg_kernel(int n) {
    int w = (blockIdx.x * blockDim.x + threadIdx.x) >> 5;
    if (w >= n) return;
    int lane = threadIdx.x & 31;
    int s = g_rowptr[w], e = g_rowptr[w + 1];

    float m1 = -INFINITY, m2 = -INFINITY, s1 = 0.f, s2 = 0.f;
    int i = s;
    for (; i + 2 <= e; i += 2) {
        int r0 = __ldg(&g_colidx[i]);
        int r1 = __ldg(&g_colidx[i + 1]);
        const float* p0 = g_msgs + (size_t)r0 * 64;
        const float* p1 = g_msgs + (size_t)r1 * 64;
        float a0 = p0[lane], a1 = p0[lane + 32];
        float b0 = p1[lane], b1 = p1[lane + 32];
        smax_upd(m1, s1, a0); smax_upd(m2, s2, a1);
        smax_upd(m1, s1, b0); smax_upd(m2, s2, b1);
    }
    if (i < e) {
        int r0 = __ldg(&g_colidx[i]);
        const float* p0 = g_msgs + (size_t)r0 * 64;
        smax_upd(m1, s1, p0[lane]); smax_upd(m2, s2, p0[lane + 32]);
    }
    if (s == e) { m1 = 0.f; m2 = 0.f; }

    const float inv = 1.f / 12.f;
    g_maxmsg[(size_t)w * 64 + lane]      = logf(1e-16f + s1) * inv + m1;
    g_maxmsg[(size_t)w * 64 + lane + 32] = logf(1e-16f + s2) * inv + m2;
}

// ---------------- update MLP (TF32 tensor cores) ----------------
// h' = h + mish([maxmsg|h]@uWi+ubi)@uWo+ubo ; K=128, N1=128, N2=64
__global__ void __launch_bounds__(256)
update_kernel(const float* __restrict__ hext, int hinsel, int houtsel, int n,
              const float* __restrict__ Wi, const float* __restrict__ bi,
              const float* __restrict__ Wo, const float* __restrict__ bo)
{
    constexpr int XST = 132;   // 128+4
    constexpr int WST = 136;   // 128+8
    extern __shared__ unsigned sm[];
    unsigned* xs = sm;                  // 64*132
    unsigned* ts = xs + 64 * XST;       // 64*132
    unsigned* ws = ts + 64 * XST;       // 16*136

    const float* hin = (hinsel == 0) ? hext : ((hinsel == 1) ? g_hA : g_hB);
    float* hout = (houtsel == 1) ? g_hA : g_hB;

    const int tid  = threadIdx.x;
    const int lane = tid & 31;
    const int warp = tid >> 5;
    const int rg   = warp & 1;
    const int cg   = warp >> 1;
    const int gid  = lane >> 2;
    const int ctg  = lane & 3;
    const int row0 = blockIdx.x * 64;

    // stage [maxmsg | h] -> xs (tf32)
    const float4* h4 = (const float4*)hin;
    const float4* mm4 = (const float4*)g_maxmsg;
    #pragma unroll
    for (int v = 0; v < 8; v++) {
        int u = tid + v * 256;
        int r = u >> 5, c4 = u & 31;
        float4 val = (c4 < 16) ? mm4[(size_t)(row0 + r) * 16 + c4]
                               : h4[(size_t)(row0 + r) * 16 + (c4 - 16)];
        ((uint4*)xs)[r * 33 + c4] = make_uint4(f2tf(val.x), f2tf(val.y), f2tf(val.z), f2tf(val.w));
    }
    __syncthreads();

    const int rb = rg * 32 + gid;

    // ---- GEMM1: [64,128]@[128,128] ----
    float acc[2][4][4];
    #pragma unroll
    for (int mt = 0; mt < 2; mt++)
        #pragma unroll
        for (int nt = 0; nt < 4; nt++)
            #pragma unroll
            for (int q = 0; q < 4; q++) acc[mt][nt][q] = 0.f;

    const float4* Wi4 = (const float4*)Wi;
    for (int kc = 0; kc < 8; kc++) {
        #pragma unroll
        for (int v = 0; v < 2; v++) {
            int u = tid + v * 256;        // [0, 512) float4 of 16x128 chunk
            int rr = u >> 5, c4 = u & 31;
            float4 w = Wi4[kc * 512 + u];
            ((uint4*)ws)[rr * 34 + c4] = make_uint4(f2tf(w.x), f2tf(w.y), f2tf(w.z), f2tf(w.w));
        }
        __syncthreads();
        #pragma unroll
        for (int ks = 0; ks < 2; ks++) {
            int acol = kc * 16 + ks * 8 + ctg;
            unsigned a[2][4];
            #pragma unroll
            for (int mt = 0; mt < 2; mt++) {
                const unsigned* ap = xs + (rb + mt * 16) * XST + acol;
                a[mt][0] = ap[0];
                a[mt][1] = ap[8 * XST];
                a[mt][2] = ap[4];
                a[mt][3] = ap[8 * XST + 4];
            }
            #pragma unroll
            for (int nt = 0; nt < 4; nt++) {
                int bcol = cg * 32 + nt * 8 + gid;
                unsigned b0 = ws[(ks * 8 + ctg) * WST + bcol];
                unsigned b1 = ws[(ks * 8 + ctg + 4) * WST + bcol];
                mma8(acc[0][nt], a[0][0], a[0][1], a[0][2], a[0][3], b0, b1);
                mma8(acc[1][nt], a[1][0], a[1][1], a[1][2], a[1][3], b0, b1);
            }
        }
        __syncthreads();
    }

    // bias + mish -> ts
    #pragma unroll
    for (int mt = 0; mt < 2; mt++) {
        int rA = rg * 32 + mt * 16 + gid;
        #pragma unroll
        for (int nt = 0; nt < 4; nt++) {
            int c0 = cg * 32 + nt * 8 + 2 * ctg;
            float b0v = __ldg(&bi[c0]), b1v = __ldg(&bi[c0 + 1]);
            ts[rA * XST + c0]           = f2tf(mishf(acc[mt][nt][0] + b0v));
            ts[rA * XST + c0 + 1]       = f2tf(mishf(acc[mt][nt][1] + b1v));
            ts[(rA + 8) * XST + c0]     = f2tf(mishf(acc[mt][nt][2] + b0v));
            ts[(rA + 8) * XST + c0 + 1] = f2tf(mishf(acc[mt][nt][3] + b1v));
        }
    }

    // ---- GEMM2: [64,128]@[128,64], residual = h (= xs cols 64..128) ----
    float acc2[2][2][4];
    #pragma unroll
    for (int mt = 0; mt < 2; mt++) {
        int rA = rg * 32 + mt * 16 + gid;
        #pragma unroll
        for (int nt = 0; nt < 2; nt++) {
            int c0 = cg * 16 + nt * 8 + 2 * ctg;
            float b0v = __ldg(&bo[c0]), b1v = __ldg(&bo[c0 + 1]);
            acc2[mt][nt][0] = __uint_as_float(xs[rA * XST + 64 + c0]) + b0v;
            acc2[mt][nt][1] = __uint_as_float(xs[rA * XST + 64 + c0 + 1]) + b1v;
            acc2[mt][nt][2] = __uint_as_float(xs[(rA + 8) * XST + 64 + c0]) + b0v;
            acc2[mt][nt][3] = __uint_as_float(xs[(rA + 8) * XST + 64 + c0 + 1]) + b1v;
        }
    }

    const float4* Wo4 = (const float4*)Wo;   // [128, 64]
    for (int kc = 0; kc < 8; kc++) {
        {
            int u = tid;                   // 16*16=256 float4
            int rr = u >> 4, c4 = u & 15;
            float4 w = Wo4[kc * 256 + u];
            ((uint4*)ws)[rr * 34 + c4] = make_uint4(f2tf(w.x), f2tf(w.y), f2tf(w.z), f2tf(w.w));
        }
        __syncthreads();
        #pragma unroll
        for (int ks = 0; ks < 2; ks++) {
            int acol = kc * 16 + ks * 8 + ctg;
            unsigned a[2][4];
            #pragma unroll
            for (int mt = 0; mt < 2; mt++) {
                const unsigned* ap = ts + (rb + mt * 16) * XST + acol;
                a[mt][0] = ap[0];
                a[mt][1] = ap[8 * XST];
                a[mt][2] = ap[4];
                a[mt][3] = ap[8 * XST + 4];
            }
            #pragma unroll
            for (int nt = 0; nt < 2; nt++) {
                int bcol = cg * 16 + nt * 8 + gid;
                unsigned b0 = ws[(ks * 8 + ctg) * WST + bcol];
                unsigned b1 = ws[(ks * 8 + ctg + 4) * WST + bcol];
                mma8(acc2[0][nt], a[0][0], a[0][1], a[0][2], a[0][3], b0, b1);
                mma8(acc2[1][nt], a[1][0], a[1][1], a[1][2], a[1][3], b0, b1);
            }
        }
        __syncthreads();
    }

    #pragma unroll
    for (int mt = 0; mt < 2; mt++) {
        int rA = row0 + rg * 32 + mt * 16 + gid;
        #pragma unroll
        for (int nt = 0; nt < 2; nt++) {
            int c0 = cg * 16 + nt * 8 + 2 * ctg;
            if (rA < n) {
                hout[(size_t)rA * 64 + c0]     = acc2[mt][nt][0];
                hout[(size_t)rA * 64 + c0 + 1] = acc2[mt][nt][1];
            }
            if (rA + 8 < n) {
                hout[(size_t)(rA + 8) * 64 + c0]     = acc2[mt][nt][2];
                hout[(size_t)(rA + 8) * 64 + c0 + 1] = acc2[mt][nt][3];
            }
        }
    }
}

// ---------------- readout ----------------
__global__ void bounds_kernel(const int* __restrict__ tok, int B) {
    if (threadIdx.x == 0) {
        int c = 0;
        g_bounds[0] = 0;
        for (int i = 0; i < B; i++) { c += tok[i]; g_bounds[i + 1] = c; }
    }
}

__global__ void segsum_kernel() {
    int b = blockIdx.x;
    int s = g_bounds[b], e = g_bounds[b + 1];
    int f = threadIdx.x & 63, g = threadIdx.x >> 6;
    float a = 0.f;
    for (int r = s + g; r < e; r += 4) a += g_hB[(size_t)r * 64 + f];
    __shared__ float red[256];
    red[threadIdx.x] = a;
    __syncthreads();
    if (g == 0) g_agg[b * 64 + f] = red[f] + red[64 + f] + red[128 + f] + red[192 + f];
}

__global__ void heads_kernel(const float* __restrict__ vWi, const float* __restrict__ vbi,
                             const float* __restrict__ vWo, const float* __restrict__ vbo,
                             const float* __restrict__ dWi, const float* __restrict__ dbi,
                             const float* __restrict__ dWo, const float* __restrict__ dbo,
                             float* __restrict__ out, int B)
{
    int b = blockIdx.x, o = threadIdx.x;   // 64 threads
    __shared__ float a[64];
    __shared__ float red[64];
    a[o] = g_agg[b * 64 + o];
    __syncthreads();

    float t = vbi[o];
    for (int i = 0; i < 64; i++) t = fmaf(a[i], vWi[i * 64 + o], t);
    red[o] = mishf(t) * vWo[o];
    __syncthreads();
    for (int s = 32; s > 0; s >>= 1) {
        if (o < s) red[o] += red[o + s];
        __syncthreads();
    }
    if (o == 0) out[b] = red[0] + vbo[0];
    __syncthreads();

    t = dbi[o];
    for (int i = 0; i < 64; i++) t = fmaf(a[i], dWi[i * 64 + o], t);
    red[o] = mishf(t) * dWo[o];
    __syncthreads();
    for (int s = 32; s > 0; s >>= 1) {
        if (o < s) red[o] += red[o + s];
        __syncthreads();
    }
    if (o == 0) out[B + b] = red[0] + dbo[0];
}

// ---------------- host launch ----------------
static inline int smem_rel(int S, int A) {
    return (2 * 64 * (S + 4) + 16 * (S + 8)) * 4 + 64 * A * 4;
}

extern "C" void kernel_launch(void* const* d_in, const int* in_sizes, int n_in,
                              void* d_out, int out_size)
{
    if (n_in < 29) return;
    const float* h0  = (const float*)d_in[0];
    const int*   a1  = (const int*)d_in[1];  int n1 = in_sizes[1];
    const int*   a2  = (const int*)d_in[2];  int n2 = in_sizes[2];
    const int*   a3  = (const int*)d_in[3];  int n3 = in_sizes[3];
    const int*   tok = (const int*)d_in[4];  int B  = in_sizes[4];
    const float* Wi1 = (const float*)d_in[5],  *bi1 = (const float*)d_in[6];
    const float* Wo1 = (const float*)d_in[7],  *bo1 = (const float*)d_in[8];
    const float* Wi2 = (const float*)d_in[9],  *bi2 = (const float*)d_in[10];
    const float* Wo2 = (const float*)d_in[11], *bo2 = (const float*)d_in[12];
    const float* Wi3 = (const float*)d_in[13], *bi3 = (const float*)d_in[14];
    const float* Wo3 = (const float*)d_in[15], *bo3 = (const float*)d_in[16];
    const float* uWi = (const float*)d_in[17], *ubi = (const float*)d_in[18];
    const float* uWo = (const float*)d_in[19], *ubo = (const float*)d_in[20];
    const float* vWi = (const float*)d_in[21], *vbi = (const float*)d_in[22];
    const float* vWo = (const float*)d_in[23], *vbo = (const float*)d_in[24];
    const float* dWi = (const float*)d_in[25], *dbi = (const float*)d_in[26];
    const float* dWo = (const float*)d_in[27], *dbo = (const float*)d_in[28];
    float* out = (float*)d_out;

    int N = in_sizes[0] / 64;
    int m1 = n1, m2 = n2 / 2, m3 = n3 / 3;

    const int SM1 = smem_rel(64, 1);
    const int SM2 = smem_rel(128, 2);
    const int SM3 = smem_rel(192, 3);
    const int SMU = (2 * 64 * 132 + 16 * 136) * 4;

    cudaFuncSetAttribute(rel_kernel<64, 1>,  cudaFuncAttributeMaxDynamicSharedMemorySize, SM1);
    cudaFuncSetAttribute(rel_kernel<128, 2>, cudaFuncAttributeMaxDynamicSharedMemorySize, SM2);
    cudaFuncSetAttribute(rel_kernel<192, 3>, cudaFuncAttributeMaxDynamicSharedMemorySize, SM3);
    cudaFuncSetAttribute(update_kernel,      cudaFuncAttributeMaxDynamicSharedMemorySize, SMU);

    // ---- CSR build ----
    zero_counts_kernel<<<(N + 255) / 256, 256>>>(N);
    count_kernel<<<512, 256>>>(a1, n1);
    count_kernel<<<512, 256>>>(a2, n2);
    count_kernel<<<512, 256>>>(a3, n3);
    scan_kernel<<<1, 1024>>>(N);
    fill_kernel<<<512, 256>>>(a1, n1, 0);
    fill_kernel<<<512, 256>>>(a2, n2, n1);
    fill_kernel<<<512, 256>>>(a3, n3, n1 + n2);

    // ---- two GNN layers ----
    for (int layer = 0; layer < 2; layer++) {
        int hsel = (layer == 0) ? 0 : 1;
        rel_kernel<64, 1><<<(m1 + 63) / 64, 256, SM1>>>(h0, hsel, a1, m1, Wi1, bi1, Wo1, bo1, 0LL);
        rel_kernel<128, 2><<<(m2 + 63) / 64, 256, SM2>>>(h0, hsel, a2, m2, Wi2, bi2, Wo2, bo2, (long long)n1 * 64);
        rel_kernel<192, 3><<<(m3 + 63) / 64, 256, SM3>>>(h0, hsel, a3, m3, Wi3, bi3, Wo3, bo3, (long long)(n1 + n2) * 64);
        agg_kernel<<<(N + 7) / 8, 256>>>(N);
        update_kernel<<<(N + 63) / 64, 256, SMU>>>(h0, hsel, (layer == 0) ? 1 : 2, N,
                                                   uWi, ubi, uWo, ubo);
    }

    // ---- readout ----
    bounds_kernel<<<1, 32>>>(tok, B);
    segsum_kernel<<<B, 256>>>();
    heads_kernel<<<B, 64>>>(vWi, vbi, vWo, vbo, dWi, dbi, dWo, dbo, out, B);
}